// round 1
// baseline (speedup 1.0000x reference)
#include <cuda_runtime.h>
#include <cuda_bf16.h>
#include <math.h>

// Problem constants
#define B_  4
#define T_  1024
#define C_  1024
#define H_  16
#define D_  64
#define E_  8
#define BOT_ 64
#define M_ (B_*T_)   // 4096 rows

// ---------------- scratch (no allocations allowed) ----------------
__device__ float g_H1 [M_*C_];
__device__ float g_Q  [M_*C_];
__device__ float g_K  [M_*C_];
__device__ float g_V  [M_*C_];
__device__ float g_Y  [M_*C_];
__device__ float g_X2 [M_*C_];
__device__ float g_H2 [M_*C_];
__device__ float g_G  [M_*4*C_];     // 4096 x 4096 gelu activations
__device__ float g_gatev[T_*2];
__device__ int   g_gatei[T_*2];

// ---------------- LayerNorm ----------------
__global__ __launch_bounds__(256) void ln_kernel(const float* __restrict__ x,
        const float* __restrict__ g, const float* __restrict__ b, float* __restrict__ o) {
    int row = blockIdx.x, tid = threadIdx.x;
    float4 v = ((const float4*)(x + (size_t)row * C_))[tid];
    float s  = v.x + v.y + v.z + v.w;
    float s2 = v.x*v.x + v.y*v.y + v.z*v.z + v.w*v.w;
    #pragma unroll
    for (int off = 16; off; off >>= 1) {
        s  += __shfl_xor_sync(0xffffffffu, s,  off);
        s2 += __shfl_xor_sync(0xffffffffu, s2, off);
    }
    __shared__ float rs[8], rq[8];
    int w = tid >> 5;
    if ((tid & 31) == 0) { rs[w] = s; rq[w] = s2; }
    __syncthreads();
    float tot = 0.f, tot2 = 0.f;
    #pragma unroll
    for (int i = 0; i < 8; i++) { tot += rs[i]; tot2 += rq[i]; }
    float mu  = tot * (1.0f / C_);
    float var = tot2 * (1.0f / C_) - mu * mu;
    float inv = rsqrtf(var + 1e-5f);
    float4 gg = ((const float4*)g)[tid];
    float4 bb = ((const float4*)b)[tid];
    float4 r;
    r.x = (v.x - mu) * inv * gg.x + bb.x;
    r.y = (v.y - mu) * inv * gg.y + bb.y;
    r.z = (v.z - mu) * inv * gg.z + bb.z;
    r.w = (v.w - mu) * inv * gg.w + bb.w;
    ((float4*)(o + (size_t)row * C_))[tid] = r;
}

// ---------------- SGEMM: C = act(A@B + bias) + R1 + R2 ----------------
// A [M,K] row-major, B [K,N] row-major. BM=BN=128, BK=16, 256 thr, 8x8/thread.
__device__ __forceinline__ float gelu_f(float v) {
    return 0.5f * v * (1.0f + erff(v * 0.70710678118654752f));
}

template<int ACT>
__global__ __launch_bounds__(256) void sgemm_kernel(
        const float* __restrict__ A, const float* __restrict__ Bm,
        const float* __restrict__ bias,
        const float* __restrict__ R1, const float* __restrict__ R2,
        float* __restrict__ Cm, int M, int N, int K) {
    __shared__ float As[16][128];
    __shared__ float Bs[16][128];
    int tid = threadIdx.x;
    int tx = tid & 15, ty = tid >> 4;
    int row0 = blockIdx.y * 128;
    int col0 = blockIdx.x * 128;
    float acc[8][8] = {};
    for (int kt = 0; kt < K; kt += 16) {
        #pragma unroll
        for (int s = 0; s < 2; s++) {
            int id = tid + s * 256;
            int r = id >> 2, c4 = (id & 3) << 2;
            float4 v = *(const float4*)&A[(size_t)(row0 + r) * K + kt + c4];
            As[c4 + 0][r] = v.x; As[c4 + 1][r] = v.y;
            As[c4 + 2][r] = v.z; As[c4 + 3][r] = v.w;
        }
        #pragma unroll
        for (int s = 0; s < 2; s++) {
            int id = tid + s * 256;
            int r = id >> 5, c4 = (id & 31) << 2;
            *(float4*)&Bs[r][c4] = *(const float4*)&Bm[(size_t)(kt + r) * N + col0 + c4];
        }
        __syncthreads();
        #pragma unroll
        for (int kk = 0; kk < 16; kk++) {
            float a[8], b[8];
            *(float4*)&a[0] = *(float4*)&As[kk][ty * 8];
            *(float4*)&a[4] = *(float4*)&As[kk][ty * 8 + 4];
            *(float4*)&b[0] = *(float4*)&Bs[kk][tx * 8];
            *(float4*)&b[4] = *(float4*)&Bs[kk][tx * 8 + 4];
            #pragma unroll
            for (int i = 0; i < 8; i++)
                #pragma unroll
                for (int j = 0; j < 8; j++)
                    acc[i][j] += a[i] * b[j];
        }
        __syncthreads();
    }
    const bool hasR1 = (R1 != nullptr), hasR2 = (R2 != nullptr);
    float bfrag[8];
    #pragma unroll
    for (int j = 0; j < 8; j++) bfrag[j] = bias[col0 + tx * 8 + j];
    #pragma unroll
    for (int i = 0; i < 8; i++) {
        int row = row0 + ty * 8 + i;
        size_t base = (size_t)row * N + col0 + tx * 8;
        float o8[8];
        #pragma unroll
        for (int j = 0; j < 8; j++) {
            float v = acc[i][j] + bfrag[j];
            if (ACT == 1) v = gelu_f(v);
            o8[j] = v;
        }
        if (hasR1) {
            float4 a = *(const float4*)&R1[base];
            float4 b = *(const float4*)&R1[base + 4];
            o8[0]+=a.x; o8[1]+=a.y; o8[2]+=a.z; o8[3]+=a.w;
            o8[4]+=b.x; o8[5]+=b.y; o8[6]+=b.z; o8[7]+=b.w;
        }
        if (hasR2) {
            float4 a = *(const float4*)&R2[base];
            float4 b = *(const float4*)&R2[base + 4];
            o8[0]+=a.x; o8[1]+=a.y; o8[2]+=a.z; o8[3]+=a.w;
            o8[4]+=b.x; o8[5]+=b.y; o8[6]+=b.z; o8[7]+=b.w;
        }
        *(float4*)&Cm[base]     = make_float4(o8[0], o8[1], o8[2], o8[3]);
        *(float4*)&Cm[base + 4] = make_float4(o8[4], o8[5], o8[6], o8[7]);
    }
}

// ---------------- Flash attention (causal, D=64, 64-query tiles) ----------------
__global__ __launch_bounds__(256) void attn_kernel(
        const float* __restrict__ Q, const float* __restrict__ Kg,
        const float* __restrict__ Vg, float* __restrict__ Y) {
    __shared__ float Qs [64][64];  // [d][q]
    __shared__ float KPs[64][64];  // K tile [d][k], later aliased as P tile [q][k]
    __shared__ float Vs [64][64];  // [k][d]
    int tid = threadIdx.x, tx = tid & 15, ty = tid >> 4;
    int qt = blockIdx.x;
    int b = blockIdx.y >> 4, h = blockIdx.y & 15;
    const int baseRow = b * T_;

    #pragma unroll
    for (int s = 0; s < 4; s++) {
        int id = tid + s * 256;
        int r = id >> 4, c4 = (id & 15) << 2;
        float4 v = *(const float4*)&Q[(size_t)(baseRow + qt * 64 + r) * C_ + h * 64 + c4];
        Qs[c4 + 0][r] = v.x; Qs[c4 + 1][r] = v.y;
        Qs[c4 + 2][r] = v.z; Qs[c4 + 3][r] = v.w;
    }
    float m_[4] = {-1e30f, -1e30f, -1e30f, -1e30f};
    float l_[4] = {0.f, 0.f, 0.f, 0.f};
    float o[4][4] = {};
    for (int kt = 0; kt <= qt; kt++) {
        __syncthreads();   // prior PV done before overwriting KPs/Vs
        #pragma unroll
        for (int s = 0; s < 4; s++) {
            int id = tid + s * 256;
            int r = id >> 4, c4 = (id & 15) << 2;
            size_t gidx = (size_t)(baseRow + kt * 64 + r) * C_ + h * 64 + c4;
            float4 kv = *(const float4*)&Kg[gidx];
            KPs[c4 + 0][r] = kv.x; KPs[c4 + 1][r] = kv.y;
            KPs[c4 + 2][r] = kv.z; KPs[c4 + 3][r] = kv.w;
            *(float4*)&Vs[r][c4] = *(const float4*)&Vg[gidx];
        }
        __syncthreads();
        float sc[4][4] = {};
        #pragma unroll 8
        for (int d = 0; d < 64; d++) {
            float4 a  = *(float4*)&Qs[d][ty * 4];
            float4 bb = *(float4*)&KPs[d][tx * 4];
            float av[4] = {a.x, a.y, a.z, a.w};
            float bv[4] = {bb.x, bb.y, bb.z, bb.w};
            #pragma unroll
            for (int i = 0; i < 4; i++)
                #pragma unroll
                for (int j = 0; j < 4; j++)
                    sc[i][j] += av[i] * bv[j];
        }
        float alpha[4];
        #pragma unroll
        for (int i = 0; i < 4; i++) {
            float sv[4];
            #pragma unroll
            for (int j = 0; j < 4; j++) {
                float v = sc[i][j] * 0.125f;           // 1/sqrt(64)
                if (kt == qt && (tx * 4 + j) > (ty * 4 + i)) v = -1e30f;
                sv[j] = v;
            }
            float mt = fmaxf(fmaxf(sv[0], sv[1]), fmaxf(sv[2], sv[3]));
            #pragma unroll
            for (int off = 8; off; off >>= 1)
                mt = fmaxf(mt, __shfl_xor_sync(0xffffffffu, mt, off, 16));
            float mn = fmaxf(m_[i], mt);
            alpha[i] = __expf(m_[i] - mn);
            float rsum = 0.f;
            #pragma unroll
            for (int j = 0; j < 4; j++) {
                sv[j] = __expf(sv[j] - mn);
                rsum += sv[j];
                sc[i][j] = sv[j];
            }
            #pragma unroll
            for (int off = 8; off; off >>= 1)
                rsum += __shfl_xor_sync(0xffffffffu, rsum, off, 16);
            l_[i] = l_[i] * alpha[i] + rsum;
            m_[i] = mn;
        }
        __syncthreads();   // all S reads of KPs done, reuse as P
        #pragma unroll
        for (int i = 0; i < 4; i++)
            *(float4*)&KPs[ty * 4 + i][tx * 4] =
                make_float4(sc[i][0], sc[i][1], sc[i][2], sc[i][3]);
        #pragma unroll
        for (int i = 0; i < 4; i++)
            #pragma unroll
            for (int j = 0; j < 4; j++) o[i][j] *= alpha[i];
        __syncthreads();
        #pragma unroll 4
        for (int k = 0; k < 64; k++) {
            float4 bv = *(float4*)&Vs[k][tx * 4];
            #pragma unroll
            for (int i = 0; i < 4; i++) {
                float a = KPs[ty * 4 + i][k];
                o[i][0] += a * bv.x; o[i][1] += a * bv.y;
                o[i][2] += a * bv.z; o[i][3] += a * bv.w;
            }
        }
    }
    #pragma unroll
    for (int i = 0; i < 4; i++) {
        float inv = 1.f / l_[i];
        *(float4*)&Y[(size_t)(baseRow + qt * 64 + ty * 4 + i) * C_ + h * 64 + tx * 4] =
            make_float4(o[i][0] * inv, o[i][1] * inv, o[i][2] * inv, o[i][3] * inv);
    }
}

// ---------------- Router: logits = X2[0] @ router; top-2 softmax gates ----------------
__global__ __launch_bounds__(256) void router_kernel(
        const float* __restrict__ X, const float* __restrict__ router,
        float* __restrict__ gv, int* __restrict__ gi) {
    int t = blockIdx.x;
    int tid = threadIdx.x, w = tid >> 5, lane = tid & 31;
    const float* xr = X + (size_t)t * C_;
    float s = 0.f;
    for (int k = lane; k < C_; k += 32) s += xr[k] * router[k * E_ + w];
    #pragma unroll
    for (int off = 16; off; off >>= 1) s += __shfl_xor_sync(0xffffffffu, s, off);
    __shared__ float lg[E_];
    if (lane == 0) lg[w] = s;
    __syncthreads();
    if (tid == 0) {
        int e0 = 0; float v0 = lg[0];
        #pragma unroll
        for (int e = 1; e < E_; e++) if (lg[e] > v0) { v0 = lg[e]; e0 = e; }
        int e1 = -1; float v1 = -3.4e38f;
        #pragma unroll
        for (int e = 0; e < E_; e++)
            if (e != e0 && lg[e] > v1) { v1 = lg[e]; e1 = e; }
        float ex = __expf(v1 - v0);
        float denom = 1.f + ex;
        gv[t * 2 + 0] = 1.f / denom;
        gv[t * 2 + 1] = ex / denom;
        gi[t * 2 + 0] = e0;
        gi[t * 2 + 1] = e1;
    }
}

// ---------------- Adapter experts: writes y_adapt into d_out ----------------
__global__ __launch_bounds__(256) void adapter_kernel(
        const float* __restrict__ X, const float* __restrict__ gv,
        const int* __restrict__ gi,
        const float* __restrict__ ad_w, const float* __restrict__ ad_b,
        const float* __restrict__ au_w, const float* __restrict__ au_b,
        float* __restrict__ out) {
    int blk = blockIdx.x;            // blk = b*T + t
    int t = blk & (T_ - 1);
    int tid = threadIdx.x;
    __shared__ float xs[C_];
    __shared__ float down[BOT_];
    __shared__ float part[256];
    ((float4*)xs)[tid] = ((const float4*)(X + (size_t)blk * C_))[tid];
    float acc[4] = {0.f, 0.f, 0.f, 0.f};
    __syncthreads();
    for (int kk = 0; kk < 2; kk++) {
        int e = gi[t * 2 + kk];
        float gsc = gv[t * 2 + kk] * 0.1f;
        const float* adw = ad_w + (size_t)e * C_ * BOT_;
        int u = tid & 63, p = tid >> 6;
        float ds = 0.f;
        int j0 = p * 256;
        #pragma unroll 8
        for (int j = j0; j < j0 + 256; j++) ds += xs[j] * adw[(size_t)j * BOT_ + u];
        part[tid] = ds;
        __syncthreads();
        if (tid < 64) {
            float d = part[tid] + part[tid + 64] + part[tid + 128] + part[tid + 192]
                    + ad_b[e * BOT_ + tid];
            down[tid] = fmaxf(d, 0.f);
        }
        __syncthreads();
        const float* auw = au_w + (size_t)e * BOT_ * C_;
        #pragma unroll
        for (int r = 0; r < 4; r++) {
            int c = r * 256 + tid;
            float s = 0.f;
            #pragma unroll 8
            for (int d = 0; d < BOT_; d++) s += down[d] * auw[(size_t)d * C_ + c];
            acc[r] += gsc * (s + au_b[e * C_ + c]);
        }
        __syncthreads();   // protect part/down before next expert
    }
    #pragma unroll
    for (int r = 0; r < 4; r++)
        out[(size_t)blk * C_ + r * 256 + tid] = acc[r];
}

// ---------------- host launch ----------------
extern "C" void kernel_launch(void* const* d_in, const int* in_sizes, int n_in,
                              void* d_out, int out_size) {
    const float* x      = (const float*)d_in[0];
    const float* Wq     = (const float*)d_in[1];
    const float* bq     = (const float*)d_in[2];
    const float* Wk     = (const float*)d_in[3];
    const float* bk     = (const float*)d_in[4];
    const float* Wv     = (const float*)d_in[5];
    const float* bv     = (const float*)d_in[6];
    const float* Wo     = (const float*)d_in[7];
    const float* bo     = (const float*)d_in[8];
    const float* ln1_g  = (const float*)d_in[9];
    const float* ln1_b  = (const float*)d_in[10];
    const float* ln2_g  = (const float*)d_in[11];
    const float* ln2_b  = (const float*)d_in[12];
    const float* mlp_w1 = (const float*)d_in[13];
    const float* mlp_b1 = (const float*)d_in[14];
    const float* mlp_w2 = (const float*)d_in[15];
    const float* mlp_b2 = (const float*)d_in[16];
    const float* router = (const float*)d_in[17];
    const float* ad_w   = (const float*)d_in[18];
    const float* ad_b   = (const float*)d_in[19];
    const float* au_w   = (const float*)d_in[20];
    const float* au_b   = (const float*)d_in[21];
    float* out = (float*)d_out;

    void *p;
    cudaGetSymbolAddress(&p, g_H1);  float* H1 = (float*)p;
    cudaGetSymbolAddress(&p, g_Q);   float* Qb = (float*)p;
    cudaGetSymbolAddress(&p, g_K);   float* Kb = (float*)p;
    cudaGetSymbolAddress(&p, g_V);   float* Vb = (float*)p;
    cudaGetSymbolAddress(&p, g_Y);   float* Yb = (float*)p;
    cudaGetSymbolAddress(&p, g_X2);  float* X2 = (float*)p;
    cudaGetSymbolAddress(&p, g_H2);  float* H2 = (float*)p;
    cudaGetSymbolAddress(&p, g_G);   float* G  = (float*)p;
    cudaGetSymbolAddress(&p, g_gatev); float* gv = (float*)p;
    cudaGetSymbolAddress(&p, g_gatei); int*   gi = (int*)p;

    // 1. h = LN1(x)
    ln_kernel<<<M_, 256>>>(x, ln1_g, ln1_b, H1);
    // 2. Q,K,V
    sgemm_kernel<0><<<dim3(C_/128, M_/128), 256>>>(H1, Wq, bq, nullptr, nullptr, Qb, M_, C_, C_);
    sgemm_kernel<0><<<dim3(C_/128, M_/128), 256>>>(H1, Wk, bk, nullptr, nullptr, Kb, M_, C_, C_);
    sgemm_kernel<0><<<dim3(C_/128, M_/128), 256>>>(H1, Wv, bv, nullptr, nullptr, Vb, M_, C_, C_);
    // 3. causal attention
    attn_kernel<<<dim3(T_/64, B_*H_), 256>>>(Qb, Kb, Vb, Yb);
    // 4. x2 = x + y @ Wo + bo
    sgemm_kernel<0><<<dim3(C_/128, M_/128), 256>>>(Yb, Wo, bo, x, nullptr, X2, M_, C_, C_);
    // 5. router gates from batch 0 of x2
    router_kernel<<<T_, 256>>>(X2, router, gv, gi);
    // 6. adapter -> d_out holds y_adapt
    adapter_kernel<<<M_, 256>>>(X2, gv, gi, ad_w, ad_b, au_w, au_b, out);
    // 7. h2 = LN2(x2)
    ln_kernel<<<M_, 256>>>(X2, ln2_g, ln2_b, H2);
    // 8. G = gelu(h2 @ W1 + b1)
    sgemm_kernel<1><<<dim3(4*C_/128, M_/128), 256>>>(H2, mlp_w1, mlp_b1, nullptr, nullptr, G, M_, 4*C_, C_);
    // 9. out = x2 + (G @ W2 + b2) + y_adapt(d_out)
    sgemm_kernel<0><<<dim3(C_/128, M_/128), 256>>>(G, mlp_w2, mlp_b2, X2, out, out, M_, C_, 4*C_);
}

// round 4
// speedup vs baseline: 2.3022x; 2.3022x over previous
#include <cuda_runtime.h>
#include <cuda_bf16.h>
#include <math.h>
#include <stdint.h>

// Problem constants
#define B_  4
#define T_  1024
#define C_  1024
#define H_  16
#define E_  8
#define BOT_ 64
#define M_ (B_*T_)   // 4096 rows

// ---------------- scratch (no allocations allowed) ----------------
__device__ float g_Q [M_*C_];
__device__ float g_K [M_*C_];
__device__ float g_V [M_*C_];
__device__ float g_X2[M_*C_];

__device__ __align__(16) __nv_bfloat16 g_H1h[M_*C_], g_H1l[M_*C_];
__device__ __align__(16) __nv_bfloat16 g_H2h[M_*C_], g_H2l[M_*C_];
__device__ __align__(16) __nv_bfloat16 g_Yh [M_*C_], g_Yl [M_*C_];
__device__ __align__(16) __nv_bfloat16 g_Gh [M_*4*C_], g_Gl [M_*4*C_];

__device__ __align__(16) __nv_bfloat16 g_WqTh[C_*C_], g_WqTl[C_*C_];
__device__ __align__(16) __nv_bfloat16 g_WkTh[C_*C_], g_WkTl[C_*C_];
__device__ __align__(16) __nv_bfloat16 g_WvTh[C_*C_], g_WvTl[C_*C_];
__device__ __align__(16) __nv_bfloat16 g_WoTh[C_*C_], g_WoTl[C_*C_];
__device__ __align__(16) __nv_bfloat16 g_W1Th[C_*4*C_], g_W1Tl[C_*4*C_];
__device__ __align__(16) __nv_bfloat16 g_W2Th[4*C_*C_], g_W2Tl[4*C_*C_];

__device__ float g_gatev[T_*2];
__device__ int   g_gatei[T_*2];

// ---------------- helpers ----------------
__device__ __forceinline__ uint32_t s2u(const void* p) {
    uint32_t a;
    asm("{ .reg .u64 t; cvta.to.shared.u64 t, %1; cvt.u32.u64 %0, t; }" : "=r"(a) : "l"(p));
    return a;
}
__device__ __forceinline__ void cp16(uint32_t s, const void* g) {
    asm volatile("cp.async.cg.shared.global [%0], [%1], 16;" :: "r"(s), "l"(g));
}
__device__ __forceinline__ void ldsm4(uint32_t* r, uint32_t a) {
    asm volatile("ldmatrix.sync.aligned.m8n8.x4.shared.b16 {%0,%1,%2,%3}, [%4];"
        : "=r"(r[0]), "=r"(r[1]), "=r"(r[2]), "=r"(r[3]) : "r"(a));
}
__device__ __forceinline__ void mma16816(float* c, const uint32_t* a, const uint32_t* b) {
    asm volatile("mma.sync.aligned.m16n8k16.row.col.f32.bf16.bf16.f32 "
        "{%0,%1,%2,%3}, {%4,%5,%6,%7}, {%8,%9}, {%0,%1,%2,%3};"
        : "+f"(c[0]), "+f"(c[1]), "+f"(c[2]), "+f"(c[3])
        : "r"(a[0]), "r"(a[1]), "r"(a[2]), "r"(a[3]), "r"(b[0]), "r"(b[1]));
}
__device__ __forceinline__ uint32_t packbf(__nv_bfloat16 a, __nv_bfloat16 b) {
    __nv_bfloat162 t(a, b);
    return *reinterpret_cast<uint32_t*>(&t);
}
__device__ __forceinline__ float gelu_f(float v) {
    return 0.5f * v * (1.0f + erff(v * 0.70710678118654752f));
}

// ---------------- GEMM: tile loaders + compute ----------------
// Stage layout: Ah[128][64], Al, Bh, Bl bf16 tiles, each 16KB (128B rows).
// Swizzle: 16B unit index = row*8 + (u ^ (row&7)).
#define SMEM_STAGE 65536
#define SMEM_GEMM  (2*SMEM_STAGE)

__device__ __forceinline__ void load_stage(uint32_t sb,
    const __nv_bfloat16* __restrict__ Ah, const __nv_bfloat16* __restrict__ Al,
    const __nv_bfloat16* __restrict__ Bh, const __nv_bfloat16* __restrict__ Bl,
    int row0, int col0, int K, int kt, int tid)
{
    const __nv_bfloat16* srcs[4];
    srcs[0] = Ah + (size_t)row0 * K + kt;
    srcs[1] = Al + (size_t)row0 * K + kt;
    srcs[2] = Bh + (size_t)col0 * K + kt;
    srcs[3] = Bl + (size_t)col0 * K + kt;
    #pragma unroll
    for (int t = 0; t < 4; t++) {
        uint32_t tb = sb + t * 16384;
        const __nv_bfloat16* s = srcs[t];
        #pragma unroll
        for (int i = 0; i < 4; i++) {
            int id = tid + i * 256;
            int r = id >> 3, u = id & 7;
            cp16(tb + ((r * 8 + (u ^ (r & 7))) << 4), s + (size_t)r * K + u * 8);
        }
    }
}

__device__ __forceinline__ void gemm_pass(uint32_t sA, uint32_t sB,
        float acc[4][4][4], int lane, int wm, int wn)
{
    #pragma unroll
    for (int ks = 0; ks < 4; ks++) {
        uint32_t a[4][4];
        #pragma unroll
        for (int i = 0; i < 4; i++) {
            int row = wm * 64 + i * 16 + (lane & 15);
            int u = ks * 2 + (lane >> 4);
            ldsm4(a[i], sA + ((row * 8 + (u ^ (row & 7))) << 4));
        }
        uint32_t b[4][2];
        #pragma unroll
        for (int f = 0; f < 2; f++) {
            int row = wn * 32 + f * 16 + (lane & 7) + ((lane >> 4) << 3);
            int u = ks * 2 + ((lane >> 3) & 1);
            uint32_t r4[4];
            ldsm4(r4, sB + ((row * 8 + (u ^ (row & 7))) << 4));
            b[f * 2][0] = r4[0]; b[f * 2][1] = r4[1];
            b[f * 2 + 1][0] = r4[2]; b[f * 2 + 1][1] = r4[3];
        }
        #pragma unroll
        for (int i = 0; i < 4; i++)
            #pragma unroll
            for (int j = 0; j < 4; j++)
                mma16816(acc[i][j], a[i], b[j]);
    }
}

// D = act(A@B^T + bias) [+R1 +R2]; bf16 hi/lo split inputs (3-pass).
template<int ACT, int SPLITOUT>
__global__ __launch_bounds__(256) void mma_gemm(
    const __nv_bfloat16* __restrict__ Ah, const __nv_bfloat16* __restrict__ Al,
    const __nv_bfloat16* __restrict__ Bh, const __nv_bfloat16* __restrict__ Bl,
    const float* __restrict__ bias,
    const float* __restrict__ R1, const float* __restrict__ R2,
    float* __restrict__ Cf, __nv_bfloat16* __restrict__ Ch, __nv_bfloat16* __restrict__ Cl,
    int M, int N, int K)
{
    extern __shared__ char smem[];
    uint32_t sb = s2u(smem);
    int tid = threadIdx.x, lane = tid & 31, w = tid >> 5;
    int wm = w & 1, wn = w >> 1;
    int row0 = blockIdx.y * 128, col0 = blockIdx.x * 128;
    float acc[4][4][4] = {};
    int nc = K >> 6;

    load_stage(sb, Ah, Al, Bh, Bl, row0, col0, K, 0, tid);
    asm volatile("cp.async.commit_group;" ::: "memory");

    for (int c = 0; c < nc; c++) {
        if (c + 1 < nc) {
            load_stage(sb + ((c + 1) & 1) * SMEM_STAGE, Ah, Al, Bh, Bl,
                       row0, col0, K, (c + 1) << 6, tid);
            asm volatile("cp.async.commit_group;" ::: "memory");
            asm volatile("cp.async.wait_group 1;" ::: "memory");
        } else {
            asm volatile("cp.async.wait_group 0;" ::: "memory");
        }
        __syncthreads();
        uint32_t st = sb + (c & 1) * SMEM_STAGE;
        gemm_pass(st,          st + 32768, acc, lane, wm, wn);   // Ah*Bh
        gemm_pass(st + 16384,  st + 32768, acc, lane, wm, wn);   // Al*Bh
        gemm_pass(st,          st + 49152, acc, lane, wm, wn);   // Ah*Bl
        __syncthreads();
    }

    // epilogue
    int gq = lane >> 2, tc2 = (lane & 3) * 2;
    #pragma unroll
    for (int i = 0; i < 4; i++) {
        #pragma unroll
        for (int rr = 0; rr < 2; rr++) {
            int row = row0 + wm * 64 + i * 16 + rr * 8 + gq;
            #pragma unroll
            for (int j = 0; j < 4; j++) {
                int col = col0 + wn * 32 + j * 8 + tc2;
                float v0 = acc[i][j][rr * 2 + 0] + bias[col];
                float v1 = acc[i][j][rr * 2 + 1] + bias[col + 1];
                if (ACT) { v0 = gelu_f(v0); v1 = gelu_f(v1); }
                size_t o = (size_t)row * N + col;
                if (!SPLITOUT) {
                    if (R1) { v0 += R1[o]; v1 += R1[o + 1]; }
                    if (R2) { v0 += R2[o]; v1 += R2[o + 1]; }
                    *(float2*)(Cf + o) = make_float2(v0, v1);
                } else {
                    __nv_bfloat16 h0 = __float2bfloat16(v0), h1 = __float2bfloat16(v1);
                    __nv_bfloat16 l0 = __float2bfloat16(v0 - __bfloat162float(h0));
                    __nv_bfloat16 l1 = __float2bfloat16(v1 - __bfloat162float(h1));
                    *(uint32_t*)(Ch + o) = packbf(h0, h1);
                    *(uint32_t*)(Cl + o) = packbf(l0, l1);
                }
            }
        }
    }
}

// ---------------- weight transpose + bf16 split: W[K,N] -> T[N,K] ----------------
__global__ __launch_bounds__(256) void transpose_split_kernel(
        const float* __restrict__ W, __nv_bfloat16* __restrict__ Th,
        __nv_bfloat16* __restrict__ Tl, int K, int N) {
    __shared__ float t[32][33];
    int tx = threadIdx.x, ty = threadIdx.y;  // 32 x 8
    int n0 = blockIdx.x * 32, k0 = blockIdx.y * 32;
    #pragma unroll
    for (int i = 0; i < 4; i++)
        t[ty + i * 8][tx] = W[(size_t)(k0 + ty + i * 8) * N + n0 + tx];
    __syncthreads();
    #pragma unroll
    for (int i = 0; i < 4; i++) {
        int n = n0 + ty + i * 8;
        int k = k0 + tx;
        float v = t[tx][ty + i * 8];
        __nv_bfloat16 h = __float2bfloat16(v);
        Th[(size_t)n * K + k] = h;
        Tl[(size_t)n * K + k] = __float2bfloat16(v - __bfloat162float(h));
    }
}

// ---------------- LayerNorm -> bf16 splits ----------------
__global__ __launch_bounds__(256) void ln_split_kernel(const float* __restrict__ x,
        const float* __restrict__ g, const float* __restrict__ b,
        __nv_bfloat16* __restrict__ Oh, __nv_bfloat16* __restrict__ Ol) {
    int row = blockIdx.x, tid = threadIdx.x;
    float4 v = ((const float4*)(x + (size_t)row * C_))[tid];
    float s  = v.x + v.y + v.z + v.w;
    float s2 = v.x*v.x + v.y*v.y + v.z*v.z + v.w*v.w;
    #pragma unroll
    for (int off = 16; off; off >>= 1) {
        s  += __shfl_xor_sync(0xffffffffu, s,  off);
        s2 += __shfl_xor_sync(0xffffffffu, s2, off);
    }
    __shared__ float rs[8], rq[8];
    int w = tid >> 5;
    if ((tid & 31) == 0) { rs[w] = s; rq[w] = s2; }
    __syncthreads();
    float tot = 0.f, tot2 = 0.f;
    #pragma unroll
    for (int i = 0; i < 8; i++) { tot += rs[i]; tot2 += rq[i]; }
    float mu  = tot * (1.0f / C_);
    float var = tot2 * (1.0f / C_) - mu * mu;
    float inv = rsqrtf(var + 1e-5f);
    float4 gg = ((const float4*)g)[tid];
    float4 bb = ((const float4*)b)[tid];
    float r0 = (v.x - mu) * inv * gg.x + bb.x;
    float r1 = (v.y - mu) * inv * gg.y + bb.y;
    float r2 = (v.z - mu) * inv * gg.z + bb.z;
    float r3 = (v.w - mu) * inv * gg.w + bb.w;
    __nv_bfloat16 h0 = __float2bfloat16(r0), h1 = __float2bfloat16(r1);
    __nv_bfloat16 h2 = __float2bfloat16(r2), h3 = __float2bfloat16(r3);
    __nv_bfloat16 l0 = __float2bfloat16(r0 - __bfloat162float(h0));
    __nv_bfloat16 l1 = __float2bfloat16(r1 - __bfloat162float(h1));
    __nv_bfloat16 l2 = __float2bfloat16(r2 - __bfloat162float(h2));
    __nv_bfloat16 l3 = __float2bfloat16(r3 - __bfloat162float(h3));
    size_t o = (size_t)row * C_ + tid * 4;
    *(uint2*)(Oh + o) = make_uint2(packbf(h0, h1), packbf(h2, h3));
    *(uint2*)(Ol + o) = make_uint2(packbf(l0, l1), packbf(l2, l3));
}

// ---------------- Flash attention (causal, D=64) -> bf16 split Y ----------------
__global__ __launch_bounds__(256) void attn_kernel(
        const float* __restrict__ Q, const float* __restrict__ Kg,
        const float* __restrict__ Vg,
        __nv_bfloat16* __restrict__ Yh, __nv_bfloat16* __restrict__ Yl) {
    __shared__ float Qs [64][64];
    __shared__ float KPs[64][64];
    __shared__ float Vs [64][64];
    int tid = threadIdx.x, tx = tid & 15, ty = tid >> 4;
    int qt = blockIdx.x;
    int bb_ = blockIdx.y >> 4, hh_ = blockIdx.y & 15;
    const int baseRow = bb_ * T_;

    #pragma unroll
    for (int s = 0; s < 4; s++) {
        int id = tid + s * 256;
        int r = id >> 4, c4 = (id & 15) << 2;
        float4 v = *(const float4*)&Q[(size_t)(baseRow + qt * 64 + r) * C_ + hh_ * 64 + c4];
        Qs[c4 + 0][r] = v.x; Qs[c4 + 1][r] = v.y;
        Qs[c4 + 2][r] = v.z; Qs[c4 + 3][r] = v.w;
    }
    float m_[4] = {-1e30f, -1e30f, -1e30f, -1e30f};
    float l_[4] = {0.f, 0.f, 0.f, 0.f};
    float o[4][4] = {};
    for (int kt = 0; kt <= qt; kt++) {
        __syncthreads();
        #pragma unroll
        for (int s = 0; s < 4; s++) {
            int id = tid + s * 256;
            int r = id >> 4, c4 = (id & 15) << 2;
            size_t gidx = (size_t)(baseRow + kt * 64 + r) * C_ + hh_ * 64 + c4;
            float4 kv = *(const float4*)&Kg[gidx];
            KPs[c4 + 0][r] = kv.x; KPs[c4 + 1][r] = kv.y;
            KPs[c4 + 2][r] = kv.z; KPs[c4 + 3][r] = kv.w;
            *(float4*)&Vs[r][c4] = *(const float4*)&Vg[gidx];
        }
        __syncthreads();
        float sc[4][4] = {};
        #pragma unroll 8
        for (int d = 0; d < 64; d++) {
            float4 a  = *(float4*)&Qs[d][ty * 4];
            float4 bv4 = *(float4*)&KPs[d][tx * 4];
            float av[4] = {a.x, a.y, a.z, a.w};
            float bv[4] = {bv4.x, bv4.y, bv4.z, bv4.w};
            #pragma unroll
            for (int i = 0; i < 4; i++)
                #pragma unroll
                for (int j = 0; j < 4; j++)
                    sc[i][j] += av[i] * bv[j];
        }
        float alpha[4];
        #pragma unroll
        for (int i = 0; i < 4; i++) {
            float sv[4];
            #pragma unroll
            for (int j = 0; j < 4; j++) {
                float v = sc[i][j] * 0.125f;
                if (kt == qt && (tx * 4 + j) > (ty * 4 + i)) v = -1e30f;
                sv[j] = v;
            }
            float mt = fmaxf(fmaxf(sv[0], sv[1]), fmaxf(sv[2], sv[3]));
            #pragma unroll
            for (int off = 8; off; off >>= 1)
                mt = fmaxf(mt, __shfl_xor_sync(0xffffffffu, mt, off, 16));
            float mn = fmaxf(m_[i], mt);
            alpha[i] = __expf(m_[i] - mn);
            float rsum = 0.f;
            #pragma unroll
            for (int j = 0; j < 4; j++) {
                sv[j] = __expf(sv[j] - mn);
                rsum += sv[j];
                sc[i][j] = sv[j];
            }
            #pragma unroll
            for (int off = 8; off; off >>= 1)
                rsum += __shfl_xor_sync(0xffffffffu, rsum, off, 16);
            l_[i] = l_[i] * alpha[i] + rsum;
            m_[i] = mn;
        }
        __syncthreads();
        #pragma unroll
        for (int i = 0; i < 4; i++)
            *(float4*)&KPs[ty * 4 + i][tx * 4] =
                make_float4(sc[i][0], sc[i][1], sc[i][2], sc[i][3]);
        #pragma unroll
        for (int i = 0; i < 4; i++)
            #pragma unroll
            for (int j = 0; j < 4; j++) o[i][j] *= alpha[i];
        __syncthreads();
        #pragma unroll 4
        for (int k = 0; k < 64; k++) {
            float4 bv = *(float4*)&Vs[k][tx * 4];
            #pragma unroll
            for (int i = 0; i < 4; i++) {
                float a = KPs[ty * 4 + i][k];
                o[i][0] += a * bv.x; o[i][1] += a * bv.y;
                o[i][2] += a * bv.z; o[i][3] += a * bv.w;
            }
        }
    }
    #pragma unroll
    for (int i = 0; i < 4; i++) {
        float inv = 1.f / l_[i];
        float v0 = o[i][0] * inv, v1 = o[i][1] * inv, v2 = o[i][2] * inv, v3 = o[i][3] * inv;
        __nv_bfloat16 h0 = __float2bfloat16(v0), h1 = __float2bfloat16(v1);
        __nv_bfloat16 h2 = __float2bfloat16(v2), h3 = __float2bfloat16(v3);
        __nv_bfloat16 l0 = __float2bfloat16(v0 - __bfloat162float(h0));
        __nv_bfloat16 l1 = __float2bfloat16(v1 - __bfloat162float(h1));
        __nv_bfloat16 l2 = __float2bfloat16(v2 - __bfloat162float(h2));
        __nv_bfloat16 l3 = __float2bfloat16(v3 - __bfloat162float(h3));
        size_t oo = (size_t)(baseRow + qt * 64 + ty * 4 + i) * C_ + hh_ * 64 + tx * 4;
        *(uint2*)(Yh + oo) = make_uint2(packbf(h0, h1), packbf(h2, h3));
        *(uint2*)(Yl + oo) = make_uint2(packbf(l0, l1), packbf(l2, l3));
    }
}

// ---------------- Router ----------------
__global__ __launch_bounds__(256) void router_kernel(
        const float* __restrict__ X, const float* __restrict__ router,
        float* __restrict__ gv, int* __restrict__ gi) {
    int t = blockIdx.x;
    int tid = threadIdx.x, w = tid >> 5, lane = tid & 31;
    const float* xr = X + (size_t)t * C_;
    float s = 0.f;
    for (int k = lane; k < C_; k += 32) s += xr[k] * router[k * E_ + w];
    #pragma unroll
    for (int off = 16; off; off >>= 1) s += __shfl_xor_sync(0xffffffffu, s, off);
    __shared__ float lg[E_];
    if (lane == 0) lg[w] = s;
    __syncthreads();
    if (tid == 0) {
        int e0 = 0; float v0 = lg[0];
        #pragma unroll
        for (int e = 1; e < E_; e++) if (lg[e] > v0) { v0 = lg[e]; e0 = e; }
        int e1 = -1; float v1 = -3.4e38f;
        #pragma unroll
        for (int e = 0; e < E_; e++)
            if (e != e0 && lg[e] > v1) { v1 = lg[e]; e1 = e; }
        float ex = __expf(v1 - v0);
        float denom = 1.f + ex;
        gv[t * 2 + 0] = 1.f / denom;
        gv[t * 2 + 1] = ex / denom;
        gi[t * 2 + 0] = e0;
        gi[t * 2 + 1] = e1;
    }
}

// ---------------- Adapter experts ----------------
__global__ __launch_bounds__(256) void adapter_kernel(
        const float* __restrict__ X, const float* __restrict__ gv,
        const int* __restrict__ gi,
        const float* __restrict__ ad_w, const float* __restrict__ ad_b,
        const float* __restrict__ au_w, const float* __restrict__ au_b,
        float* __restrict__ out) {
    int blk = blockIdx.x;
    int t = blk & (T_ - 1);
    int tid = threadIdx.x;
    __shared__ float xs[C_];
    __shared__ float down[BOT_];
    __shared__ float part[256];
    ((float4*)xs)[tid] = ((const float4*)(X + (size_t)blk * C_))[tid];
    float acc[4] = {0.f, 0.f, 0.f, 0.f};
    __syncthreads();
    for (int kk = 0; kk < 2; kk++) {
        int e = gi[t * 2 + kk];
        float gsc = gv[t * 2 + kk] * 0.1f;
        const float* adw = ad_w + (size_t)e * C_ * BOT_;
        int u = tid & 63, p = tid >> 6;
        float ds = 0.f;
        int j0 = p * 256;
        #pragma unroll 8
        for (int j = j0; j < j0 + 256; j++) ds += xs[j] * adw[(size_t)j * BOT_ + u];
        part[tid] = ds;
        __syncthreads();
        if (tid < 64) {
            float d = part[tid] + part[tid + 64] + part[tid + 128] + part[tid + 192]
                    + ad_b[e * BOT_ + tid];
            down[tid] = fmaxf(d, 0.f);
        }
        __syncthreads();
        const float* auw = au_w + (size_t)e * BOT_ * C_;
        #pragma unroll
        for (int r = 0; r < 4; r++) {
            int c = r * 256 + tid;
            float s = 0.f;
            #pragma unroll 8
            for (int d = 0; d < BOT_; d++) s += down[d] * auw[(size_t)d * C_ + c];
            acc[r] += gsc * (s + au_b[e * C_ + c]);
        }
        __syncthreads();
    }
    #pragma unroll
    for (int r = 0; r < 4; r++)
        out[(size_t)blk * C_ + r * 256 + tid] = acc[r];
}

// ---------------- host launch ----------------
extern "C" void kernel_launch(void* const* d_in, const int* in_sizes, int n_in,
                              void* d_out, int out_size) {
    const float* x      = (const float*)d_in[0];
    const float* Wq     = (const float*)d_in[1];
    const float* bq     = (const float*)d_in[2];
    const float* Wk     = (const float*)d_in[3];
    const float* bk     = (const float*)d_in[4];
    const float* Wv     = (const float*)d_in[5];
    const float* bv     = (const float*)d_in[6];
    const float* Wo     = (const float*)d_in[7];
    const float* bo     = (const float*)d_in[8];
    const float* ln1_g  = (const float*)d_in[9];
    const float* ln1_b  = (const float*)d_in[10];
    const float* ln2_g  = (const float*)d_in[11];
    const float* ln2_b  = (const float*)d_in[12];
    const float* mlp_w1 = (const float*)d_in[13];
    const float* mlp_b1 = (const float*)d_in[14];
    const float* mlp_w2 = (const float*)d_in[15];
    const float* mlp_b2 = (const float*)d_in[16];
    const float* router = (const float*)d_in[17];
    const float* ad_w   = (const float*)d_in[18];
    const float* ad_b   = (const float*)d_in[19];
    const float* au_w   = (const float*)d_in[20];
    const float* au_b   = (const float*)d_in[21];
    float* out = (float*)d_out;

    void* p;
    cudaGetSymbolAddress(&p, g_Q);    float* Qb = (float*)p;
    cudaGetSymbolAddress(&p, g_K);    float* Kb = (float*)p;
    cudaGetSymbolAddress(&p, g_V);    float* Vb = (float*)p;
    cudaGetSymbolAddress(&p, g_X2);   float* X2 = (float*)p;
    cudaGetSymbolAddress(&p, g_H1h);  __nv_bfloat16* H1h = (__nv_bfloat16*)p;
    cudaGetSymbolAddress(&p, g_H1l);  __nv_bfloat16* H1l = (__nv_bfloat16*)p;
    cudaGetSymbolAddress(&p, g_H2h);  __nv_bfloat16* H2h = (__nv_bfloat16*)p;
    cudaGetSymbolAddress(&p, g_H2l);  __nv_bfloat16* H2l = (__nv_bfloat16*)p;
    cudaGetSymbolAddress(&p, g_Yh);   __nv_bfloat16* Yh = (__nv_bfloat16*)p;
    cudaGetSymbolAddress(&p, g_Yl);   __nv_bfloat16* Yl = (__nv_bfloat16*)p;
    cudaGetSymbolAddress(&p, g_Gh);   __nv_bfloat16* Gh = (__nv_bfloat16*)p;
    cudaGetSymbolAddress(&p, g_Gl);   __nv_bfloat16* Gl = (__nv_bfloat16*)p;
    cudaGetSymbolAddress(&p, g_WqTh); __nv_bfloat16* WqTh = (__nv_bfloat16*)p;
    cudaGetSymbolAddress(&p, g_WqTl); __nv_bfloat16* WqTl = (__nv_bfloat16*)p;
    cudaGetSymbolAddress(&p, g_WkTh); __nv_bfloat16* WkTh = (__nv_bfloat16*)p;
    cudaGetSymbolAddress(&p, g_WkTl); __nv_bfloat16* WkTl = (__nv_bfloat16*)p;
    cudaGetSymbolAddress(&p, g_WvTh); __nv_bfloat16* WvTh = (__nv_bfloat16*)p;
    cudaGetSymbolAddress(&p, g_WvTl); __nv_bfloat16* WvTl = (__nv_bfloat16*)p;
    cudaGetSymbolAddress(&p, g_WoTh); __nv_bfloat16* WoTh = (__nv_bfloat16*)p;
    cudaGetSymbolAddress(&p, g_WoTl); __nv_bfloat16* WoTl = (__nv_bfloat16*)p;
    cudaGetSymbolAddress(&p, g_W1Th); __nv_bfloat16* W1Th = (__nv_bfloat16*)p;
    cudaGetSymbolAddress(&p, g_W1Tl); __nv_bfloat16* W1Tl = (__nv_bfloat16*)p;
    cudaGetSymbolAddress(&p, g_W2Th); __nv_bfloat16* W2Th = (__nv_bfloat16*)p;
    cudaGetSymbolAddress(&p, g_W2Tl); __nv_bfloat16* W2Tl = (__nv_bfloat16*)p;
    cudaGetSymbolAddress(&p, g_gatev); float* gv = (float*)p;
    cudaGetSymbolAddress(&p, g_gatei); int*   gi = (int*)p;

    cudaFuncSetAttribute(mma_gemm<0,0>, cudaFuncAttributeMaxDynamicSharedMemorySize, SMEM_GEMM);
    cudaFuncSetAttribute(mma_gemm<1,1>, cudaFuncAttributeMaxDynamicSharedMemorySize, SMEM_GEMM);

    dim3 tpb(32, 8);
    // weight transposes + splits
    transpose_split_kernel<<<dim3(C_/32, C_/32), tpb>>>(Wq, WqTh, WqTl, C_, C_);
    transpose_split_kernel<<<dim3(C_/32, C_/32), tpb>>>(Wk, WkTh, WkTl, C_, C_);
    transpose_split_kernel<<<dim3(C_/32, C_/32), tpb>>>(Wv, WvTh, WvTl, C_, C_);
    transpose_split_kernel<<<dim3(C_/32, C_/32), tpb>>>(Wo, WoTh, WoTl, C_, C_);
    transpose_split_kernel<<<dim3(4*C_/32, C_/32), tpb>>>(mlp_w1, W1Th, W1Tl, C_, 4*C_);
    transpose_split_kernel<<<dim3(C_/32, 4*C_/32), tpb>>>(mlp_w2, W2Th, W2Tl, 4*C_, C_);

    // 1. h1 = LN1(x) -> splits
    ln_split_kernel<<<M_, 256>>>(x, ln1_g, ln1_b, H1h, H1l);
    // 2. Q, K, V (fp32 out)
    mma_gemm<0,0><<<dim3(C_/128, M_/128), 256, SMEM_GEMM>>>(H1h, H1l, WqTh, WqTl, bq, nullptr, nullptr, Qb, nullptr, nullptr, M_, C_, C_);
    mma_gemm<0,0><<<dim3(C_/128, M_/128), 256, SMEM_GEMM>>>(H1h, H1l, WkTh, WkTl, bk, nullptr, nullptr, Kb, nullptr, nullptr, M_, C_, C_);
    mma_gemm<0,0><<<dim3(C_/128, M_/128), 256, SMEM_GEMM>>>(H1h, H1l, WvTh, WvTl, bv, nullptr, nullptr, Vb, nullptr, nullptr, M_, C_, C_);
    // 3. attention -> Y splits
    attn_kernel<<<dim3(T_/64, B_*H_), 256>>>(Qb, Kb, Vb, Yh, Yl);
    // 4. x2 = x + y @ Wo + bo
    mma_gemm<0,0><<<dim3(C_/128, M_/128), 256, SMEM_GEMM>>>(Yh, Yl, WoTh, WoTl, bo, x, nullptr, X2, nullptr, nullptr, M_, C_, C_);
    // 5. router gates
    router_kernel<<<T_, 256>>>(X2, router, gv, gi);
    // 6. adapter -> d_out holds y_adapt
    adapter_kernel<<<M_, 256>>>(X2, gv, gi, ad_w, ad_b, au_w, au_b, out);
    // 7. h2 = LN2(x2) -> splits
    ln_split_kernel<<<M_, 256>>>(X2, ln2_g, ln2_b, H2h, H2l);
    // 8. G = gelu(h2 @ W1 + b1) -> splits
    mma_gemm<1,1><<<dim3(4*C_/128, M_/128), 256, SMEM_GEMM>>>(H2h, H2l, W1Th, W1Tl, mlp_b1, nullptr, nullptr, nullptr, Gh, Gl, M_, 4*C_, C_);
    // 9. out = x2 + (G @ W2 + b2) + y_adapt
    mma_gemm<0,0><<<dim3(C_/128, M_/128), 256, SMEM_GEMM>>>(Gh, Gl, W2Th, W2Tl, mlp_b2, X2, out, out, nullptr, nullptr, M_, C_, 4*C_);
}